// round 1
// baseline (speedup 1.0000x reference)
#include <cuda_runtime.h>

#define BB 16
#define CC 64
#define SS 4096

// Scratch (device globals — allocation-free per harness rules)
__device__ float g_Qt[BB * CC * SS]; // [b][c][s]  (transposed Q)
__device__ float g_Kt[BB * CC * SS]; // [b][c][s]  (transposed K)
__device__ float g_V [BB * SS * CC]; // [b][s][c]
__device__ float g_O [BB * SS * CC]; // [b][s][c]  (attention output, pre-proj)

// ---------------------------------------------------------------------------
// Kernel 1: QKV projections.  Q,K written transposed [c][s]; V natural [s][c].
// grid (64, 16), 256 threads. Each block: 64 tokens of one batch.
// ---------------------------------------------------------------------------
__global__ __launch_bounds__(256) void qkv_kernel(
    const float* __restrict__ x,
    const float* __restrict__ qw, const float* __restrict__ qb,
    const float* __restrict__ kw, const float* __restrict__ kb,
    const float* __restrict__ vw, const float* __restrict__ vb)
{
    __shared__ float xs[CC * 64];  // [c][t]
    __shared__ float ws[CC * CC];  // [o][c]
    __shared__ float bs[CC];

    const int b  = blockIdx.y;
    const int s0 = blockIdx.x * 64;
    const int tid = threadIdx.x;

    const float* xb = x + (size_t)b * CC * SS;
    for (int i = tid; i < CC * 64; i += 256) {
        int c = i >> 6, t = i & 63;
        xs[c * 64 + t] = xb[c * SS + s0 + t];   // coalesced over t
    }

    const int t = tid & 63;     // token
    const int g = tid >> 6;     // output-channel group (4 groups x 16)

    for (int w = 0; w < 3; ++w) {
        const float* W  = (w == 0) ? qw : (w == 1 ? kw : vw);
        const float* Bv = (w == 0) ? qb : (w == 1 ? kb : vb);
        __syncthreads();  // protect ws/bs reuse from previous iteration
        for (int i = tid; i < CC * CC; i += 256) ws[i] = W[i];
        if (tid < CC) bs[tid] = Bv[tid];
        __syncthreads();

        float acc[16];
        #pragma unroll
        for (int j = 0; j < 16; ++j) acc[j] = bs[g * 16 + j];

        #pragma unroll 4
        for (int c = 0; c < CC; ++c) {
            float xv = xs[c * 64 + t];
            #pragma unroll
            for (int j = 0; j < 16; ++j)
                acc[j] += xv * ws[(g * 16 + j) * CC + c];
        }

        if (w < 2) {
            float* dst = (w == 0 ? g_Qt : g_Kt) + (size_t)b * CC * SS;
            #pragma unroll
            for (int j = 0; j < 16; ++j)
                dst[(size_t)(g * 16 + j) * SS + s0 + t] = acc[j];  // coalesced over t
        } else {
            float* dst = g_V + ((size_t)b * SS + s0 + t) * CC;
            #pragma unroll
            for (int j = 0; j < 16; ++j)
                dst[g * 16 + j] = acc[j];
        }
    }
}

// ---------------------------------------------------------------------------
// Kernel 2: flash attention, fp32, BM=BN=64, d=64.
// grid (64, 16), 256 threads; thread (ty,tx)=(tid>>4, tid&15);
// QK micro-tile: q = ty*4..+3, k = tx*4..+3.  PV: q = ty*4..+3, c = tx*4..+3.
// Online softmax fully in registers via 16-lane shfl reductions.
// Smem = Qs + (K/V shared buffer) + P = exactly 48 KB, all conflict-free.
// ---------------------------------------------------------------------------
__global__ __launch_bounds__(256) void attn_kernel()
{
    __shared__ float Qs [CC * 64];   // [c][q]
    __shared__ float KVs[CC * 64];   // K phase: [c][k]; V phase: [k][c]
    __shared__ float Ps [64 * 64];   // [q][k]

    const int b  = blockIdx.y;
    const int q0 = blockIdx.x * 64;
    const int tid = threadIdx.x;
    const int ty = tid >> 4;
    const int tx = tid & 15;

    const float* Qtb = g_Qt + (size_t)b * CC * SS;
    const float* Ktb = g_Kt + (size_t)b * CC * SS;
    const float* Vb  = g_V  + (size_t)b * SS * CC;

    for (int i = tid; i < CC * 64; i += 256) {
        int c = i >> 6, q = i & 63;
        Qs[c * 64 + q] = Qtb[c * SS + q0 + q];  // coalesced; no transpose needed
    }

    float m[4], l[4], out[4][4];
    #pragma unroll
    for (int i = 0; i < 4; ++i) {
        m[i] = -1e30f; l[i] = 0.f;
        #pragma unroll
        for (int j = 0; j < 4; ++j) out[i][j] = 0.f;
    }

    const float scale = 0.125f;  // 1/sqrt(64)

    for (int kb = 0; kb < SS / 64; ++kb) {
        const int k0 = kb * 64;

        __syncthreads();  // (A) prev PV done reading KVs(V) and Ps
        for (int i = tid; i < CC * 64; i += 256) {
            int c = i >> 6, k = i & 63;
            KVs[c * 64 + k] = Ktb[c * SS + k0 + k];  // K tile, [c][k]
        }
        __syncthreads();  // (B) K ready

        // ---- S = Q K^T ----
        float sv[4][4];
        #pragma unroll
        for (int i = 0; i < 4; ++i)
            #pragma unroll
            for (int j = 0; j < 4; ++j) sv[i][j] = 0.f;

        #pragma unroll 4
        for (int c = 0; c < CC; ++c) {
            float4 qv = *(const float4*)&Qs [c * 64 + ty * 4];
            float4 kv = *(const float4*)&KVs[c * 64 + tx * 4];
            float qa[4] = {qv.x, qv.y, qv.z, qv.w};
            float ka[4] = {kv.x, kv.y, kv.z, kv.w};
            #pragma unroll
            for (int i = 0; i < 4; ++i)
                #pragma unroll
                for (int j = 0; j < 4; ++j)
                    sv[i][j] += qa[i] * ka[j];
        }

        // ---- online softmax (registers + 16-lane shfl) ----
        #pragma unroll
        for (int i = 0; i < 4; ++i) {
            #pragma unroll
            for (int j = 0; j < 4; ++j) sv[i][j] *= scale;
            float mx = fmaxf(fmaxf(sv[i][0], sv[i][1]), fmaxf(sv[i][2], sv[i][3]));
            #pragma unroll
            for (int off = 8; off; off >>= 1)
                mx = fmaxf(mx, __shfl_xor_sync(0xffffffffu, mx, off));
            float mn = fmaxf(m[i], mx);
            float alpha = __expf(m[i] - mn);
            m[i] = mn;
            float rs = 0.f;
            #pragma unroll
            for (int j = 0; j < 4; ++j) {
                float p = __expf(sv[i][j] - mn);
                sv[i][j] = p;
                rs += p;
            }
            #pragma unroll
            for (int off = 8; off; off >>= 1)
                rs += __shfl_xor_sync(0xffffffffu, rs, off);
            l[i] = l[i] * alpha + rs;
            #pragma unroll
            for (int j = 0; j < 4; ++j) out[i][j] *= alpha;
        }

        __syncthreads();  // (C) all done reading K from KVs

        #pragma unroll
        for (int i = 0; i < 4; ++i)
            *(float4*)&Ps[(ty * 4 + i) * 64 + tx * 4] =
                make_float4(sv[i][0], sv[i][1], sv[i][2], sv[i][3]);

        for (int i = tid; i < 64 * CC; i += 256) {
            int k = i >> 6, c = i & 63;
            KVs[k * 64 + c] = Vb[(size_t)(k0 + k) * CC + c];  // V tile, [k][c]
        }
        __syncthreads();  // (D) Ps + V ready

        // ---- out += P V ----
        #pragma unroll 4
        for (int k = 0; k < 64; ++k) {
            float4 vv = *(const float4*)&KVs[k * 64 + tx * 4];
            float va[4] = {vv.x, vv.y, vv.z, vv.w};
            #pragma unroll
            for (int i = 0; i < 4; ++i) {
                float p = Ps[(ty * 4 + i) * 64 + k];  // broadcast across tx lanes
                out[i][0] += p * va[0];
                out[i][1] += p * va[1];
                out[i][2] += p * va[2];
                out[i][3] += p * va[3];
            }
        }
    }

    float* Ob = g_O + ((size_t)b * SS + q0) * CC;
    #pragma unroll
    for (int i = 0; i < 4; ++i) {
        float inv = 1.f / l[i];
        *(float4*)&Ob[(ty * 4 + i) * CC + tx * 4] =
            make_float4(out[i][0] * inv, out[i][1] * inv,
                        out[i][2] * inv, out[i][3] * inv);
    }
}

// ---------------------------------------------------------------------------
// Kernel 3: output 1x1 conv + bias, writes y as [b][o][s] (coalesced over s).
// ---------------------------------------------------------------------------
__global__ __launch_bounds__(256) void proj_kernel(
    const float* __restrict__ ow, const float* __restrict__ ob,
    float* __restrict__ y)
{
    __shared__ float Os[64 * 65];   // [s][c], padded to kill conflicts
    __shared__ float ws[CC * CC];   // [o][c]
    __shared__ float bs[CC];

    const int b  = blockIdx.y;
    const int s0 = blockIdx.x * 64;
    const int tid = threadIdx.x;

    const float* Obp = g_O + ((size_t)b * SS + s0) * CC;
    for (int i = tid; i < 64 * CC; i += 256) {
        int s = i >> 6, c = i & 63;
        Os[s * 65 + c] = Obp[s * CC + c];
    }
    for (int i = tid; i < CC * CC; i += 256) ws[i] = ow[i];
    if (tid < CC) bs[tid] = ob[tid];
    __syncthreads();

    const int t = tid & 63;
    const int g = tid >> 6;

    float acc[16];
    #pragma unroll
    for (int j = 0; j < 16; ++j) acc[j] = bs[g * 16 + j];

    #pragma unroll 4
    for (int c = 0; c < CC; ++c) {
        float xv = Os[t * 65 + c];
        #pragma unroll
        for (int j = 0; j < 16; ++j)
            acc[j] += xv * ws[(g * 16 + j) * CC + c];
    }

    float* dst = y + (size_t)b * CC * SS;
    #pragma unroll
    for (int j = 0; j < 16; ++j)
        dst[(size_t)(g * 16 + j) * SS + s0 + t] = acc[j];
}

// ---------------------------------------------------------------------------
extern "C" void kernel_launch(void* const* d_in, const int* in_sizes, int n_in,
                              void* d_out, int out_size)
{
    const float* x  = (const float*)d_in[0];
    const float* qw = (const float*)d_in[1];
    const float* qb = (const float*)d_in[2];
    const float* kw = (const float*)d_in[3];
    const float* kb = (const float*)d_in[4];
    const float* vw = (const float*)d_in[5];
    const float* vb = (const float*)d_in[6];
    const float* ow = (const float*)d_in[7];
    const float* ob = (const float*)d_in[8];
    float* y = (float*)d_out;

    dim3 grid(SS / 64, BB);
    qkv_kernel <<<grid, 256>>>(x, qw, qb, kw, kb, vw, vb);
    attn_kernel<<<grid, 256>>>();
    proj_kernel<<<grid, 256>>>(ow, ob, y);
}